// round 11
// baseline (speedup 1.0000x reference)
#include <cuda_runtime.h>
#include <cstdint>

// Problem constants
#define Bn  128
#define Tn  512
#define In  128
#define Hn  512
#define NCn 100
#define Vn  101   // NC+1 token values

// Recurrent kernel tiling: 128 blocks = 8 row-tiles (16 batches) x 16 col-tiles (32 h)
#define GRID_R 128
#define THR_R  256          // 8 warps, 16 half-warp K-slices of 32 kk
#define WS_FLOATS (512*64)          // B tile (128KB)
#define AST_FLOATS (512*16)         // A tile transposed AsT[k][r] (32KB)
#define PS_FLOATS (8*16*64)         // 8 partial slots (32KB)
#define SMEM_R_BYTES ((WS_FLOATS + AST_FLOATS + PS_FLOATS) * 4)   // 196608 B

typedef unsigned long long ull;

// packed dual-fp32 ops (sm_100+)
#define FMA2(accv, av, bv) \
    asm("fma.rn.f32x2 %0, %1, %2, %0;" : "+l"(accv) : "l"(av), "l"(bv))
#define ADD2(accv, bv) \
    asm("add.rn.f32x2 %0, %0, %1;" : "+l"(accv) : "l"(bv))
#define PACK_DUP(dst, s) \
    asm("mov.b64 %0, {%1, %1};" : "=l"(dst) : "f"(s))

// ---------------- device-global scratch ----------------
__device__ float d_gtab[Vn * 4 * Hn];     // [tok][gate f,i,o,sig(c)][h]
__device__ float d_Wpack[Hn * 2 * Hn];    // [k][2h+g] g=0:f g=1:i
__device__ float d_CT[2][Hn * Bn];        // TRANSPOSED cell state: [h][b], double-buffered
__device__ float d_Hf[Bn * Hn];
__device__ unsigned int d_barArr[8 * 32]; // per-row-group monotonic counters

__device__ __forceinline__ float sigf(float x) { return 1.0f / (1.0f + expf(-x)); }

// ---------------- init ----------------
__global__ void k_init() {
    int i = blockIdx.x * blockDim.x + threadIdx.x;
    if (i < Bn * Hn) d_CT[0][i] = 0.0f;
    if (i < 8 * 32) d_barArr[i] = 0u;
}

// ---------------- token gate table ----------------
__global__ void k_gtab(const float* __restrict__ emb,
                       const float* __restrict__ Wfx, const float* __restrict__ bf,
                       const float* __restrict__ Wix, const float* __restrict__ bi,
                       const float* __restrict__ Wox, const float* __restrict__ bo,
                       const float* __restrict__ Wcx, const float* __restrict__ bc) {
    __shared__ float es[In];
    int v = blockIdx.x;
    int tid = threadIdx.x;                // 256
    if (tid < In) es[tid] = emb[v * In + tid];
    __syncthreads();
    for (int h = tid; h < Hn; h += 256) {
        float af = bf[h], ai = bi[h], ao = bo[h], ac = bc[h];
        #pragma unroll 4
        for (int k = 0; k < In; k++) {
            float e = es[k];
            af = fmaf(e, Wfx[k * Hn + h], af);
            ai = fmaf(e, Wix[k * Hn + h], ai);
            ao = fmaf(e, Wox[k * Hn + h], ao);
            ac = fmaf(e, Wcx[k * Hn + h], ac);
        }
        d_gtab[v * 2048 + h]        = af;
        d_gtab[v * 2048 + 512 + h]  = ai;
        d_gtab[v * 2048 + 1024 + h] = ao;
        d_gtab[v * 2048 + 1536 + h] = sigf(ac);   // c_tilde pre-sigmoid (no recurrent term)
    }
}

// ---------------- pack Wfc/Wic interleaved by output column ----------------
__global__ void k_wpack(const float* __restrict__ Wfc, const float* __restrict__ Wic) {
    int i = blockIdx.x * blockDim.x + threadIdx.x;   // over H*H
    if (i < Hn * Hn) {
        int k = i / Hn, h = i % Hn;
        d_Wpack[k * 1024 + 2 * h]     = Wfc[i];
        d_Wpack[k * 1024 + 2 * h + 1] = Wic[i];
    }
}

// ---------------- persistent recurrent kernel ----------------
__global__ void __launch_bounds__(THR_R, 1) k_recur(const int* __restrict__ xIdx) {
    extern __shared__ float sm[];
    float* Ws  = sm;                        // [512][64]
    float* AsT = sm + WS_FLOATS;            // [512][16]
    float* Ps  = AsT + AST_FLOATS;          // [8][16][64]

    const int tid = threadIdx.x;
    const int bx  = blockIdx.x;
    const int rb  = bx >> 4;              // 0..7  row tile (16 batches)
    const int cb  = bx & 15;              // 0..15 col tile (32 h-units)
    const int b0  = rb * 16;
    const int u0  = cb * 32;
    const int n0  = cb * 64;

    // Stage resident B tile (Wpack columns n0..n0+63) once
    for (int li = tid; li < 512 * 16; li += THR_R) {
        int k  = li >> 4;
        int c4 = (li & 15) << 2;
        float4 v = *(const float4*)(d_Wpack + k * 1024 + n0 + c4);
        *(float4*)(Ws + k * 64 + c4) = v;
    }
    __syncthreads();

    const int wid  = tid >> 5;            // 0..7
    const int lane = tid & 31;
    const int half = lane >> 4;           // 0/1
    const int hl   = lane & 15;
    const int rg   = hl & 1;              // rows rg*8 .. +8
    const int cg   = hl >> 1;             // cols cg*8 .. +8
    const int ks   = (wid * 2 + half) * 32;   // K-slice base (32 kk)

    // epilogue: 2 outputs per thread, oid = q*256 + tid ; r = tid&15, u = oid>>4
    const int er  = tid & 15;
    const int eu0 = tid >> 4;             // q=0 -> u = eu0 ; q=1 -> u = eu0+16
    const int eb  = b0 + er;

    unsigned int* barp = &d_barArr[rb * 32];

    #pragma unroll 1
    for (int t = 0; t < Tn; t++) {
        const float* CTsrc = d_CT[t & 1];

        // ---- prefetch token, gate-table values, Cold (independent of staging) ----
        int   tok  = xIdx[eb * Tn + t];
        float gfA  = d_gtab[tok * 2048 + u0 + eu0];
        float giA  = d_gtab[tok * 2048 + 512 + u0 + eu0];
        float ctA  = d_gtab[tok * 2048 + 1536 + u0 + eu0];
        float ColdA = __ldcg(&CTsrc[(u0 + eu0) * Bn + eb]);
        float gfB  = d_gtab[tok * 2048 + u0 + eu0 + 16];
        float giB  = d_gtab[tok * 2048 + 512 + u0 + eu0 + 16];
        float ctB  = d_gtab[tok * 2048 + 1536 + u0 + eu0 + 16];
        float ColdB = __ldcg(&CTsrc[(u0 + eu0 + 16) * Bn + eb]);

        // ---- stage A tile: AsT[k][0..15] = CT[k][b0..b0+16] (straight float4 copies) ----
        #pragma unroll
        for (int it = 0; it < 8; it++) {
            int li  = tid + it * THR_R;   // 0..2047
            int k   = li >> 2;
            int seg = (li & 3) << 2;
            float4 v = __ldcg((const float4*)(CTsrc + k * Bn + b0 + seg));
            *(float4*)(AsT + k * 16 + seg) = v;
        }
        __syncthreads();

        // ---- GEMM: per lane 8 rows x 8 cols over its 32-kk K-slice ----
        ull acc[8][4];
        #pragma unroll
        for (int j = 0; j < 8; j++)
            #pragma unroll
            for (int p = 0; p < 4; p++) acc[j][p] = 0ull;

        const float* Ap = AsT + ks * 16 + rg * 8;
        const float* Bp = Ws + ks * 64 + cg * 8;

        #pragma unroll 8
        for (int kk = 0; kk < 32; kk++) {
            float4     a0 = *(const float4*)(Ap + kk * 16);
            float4     a1 = *(const float4*)(Ap + kk * 16 + 4);
            ulonglong2 bv0 = *(const ulonglong2*)(Bp + kk * 64);
            ulonglong2 bv1 = *(const ulonglong2*)(Bp + kk * 64 + 4);
            ull ad;
            PACK_DUP(ad, a0.x);
            FMA2(acc[0][0], ad, bv0.x); FMA2(acc[0][1], ad, bv0.y);
            FMA2(acc[0][2], ad, bv1.x); FMA2(acc[0][3], ad, bv1.y);
            PACK_DUP(ad, a0.y);
            FMA2(acc[1][0], ad, bv0.x); FMA2(acc[1][1], ad, bv0.y);
            FMA2(acc[1][2], ad, bv1.x); FMA2(acc[1][3], ad, bv1.y);
            PACK_DUP(ad, a0.z);
            FMA2(acc[2][0], ad, bv0.x); FMA2(acc[2][1], ad, bv0.y);
            FMA2(acc[2][2], ad, bv1.x); FMA2(acc[2][3], ad, bv1.y);
            PACK_DUP(ad, a0.w);
            FMA2(acc[3][0], ad, bv0.x); FMA2(acc[3][1], ad, bv0.y);
            FMA2(acc[3][2], ad, bv1.x); FMA2(acc[3][3], ad, bv1.y);
            PACK_DUP(ad, a1.x);
            FMA2(acc[4][0], ad, bv0.x); FMA2(acc[4][1], ad, bv0.y);
            FMA2(acc[4][2], ad, bv1.x); FMA2(acc[4][3], ad, bv1.y);
            PACK_DUP(ad, a1.y);
            FMA2(acc[5][0], ad, bv0.x); FMA2(acc[5][1], ad, bv0.y);
            FMA2(acc[5][2], ad, bv1.x); FMA2(acc[5][3], ad, bv1.y);
            PACK_DUP(ad, a1.z);
            FMA2(acc[6][0], ad, bv0.x); FMA2(acc[6][1], ad, bv0.y);
            FMA2(acc[6][2], ad, bv1.x); FMA2(acc[6][3], ad, bv1.y);
            PACK_DUP(ad, a1.w);
            FMA2(acc[7][0], ad, bv0.x); FMA2(acc[7][1], ad, bv0.y);
            FMA2(acc[7][2], ad, bv1.x); FMA2(acc[7][3], ad, bv1.y);
        }

        // ---- combine the two 16-lane halves (different K-slices, same tile) ----
        #pragma unroll
        for (int j = 0; j < 8; j++)
            #pragma unroll
            for (int p = 0; p < 4; p++) {
                ull o = __shfl_xor_sync(0xffffffffu, acc[j][p], 16);
                ADD2(acc[j][p], o);
            }

        // ---- lanes 0..15 write combined partials to slot wid ----
        if (half == 0) {
            #pragma unroll
            for (int j = 0; j < 8; j++) {
                int r = rg * 8 + j;
                *(ulonglong2*)(Ps + wid * 1024 + r * 64 + cg * 8) =
                    make_ulonglong2(acc[j][0], acc[j][1]);
                *(ulonglong2*)(Ps + wid * 1024 + r * 64 + cg * 8 + 4) =
                    make_ulonglong2(acc[j][2], acc[j][3]);
            }
        }
        __syncthreads();

        // ---- tree-reduce 8 slots + gate epilogue + transposed C store ----
        float* CTdst = d_CT[(t + 1) & 1];
        #pragma unroll
        for (int q = 0; q < 2; q++) {
            int u = eu0 + q * 16;          // local h-unit 0..31
            const ull* pp = (const ull*)Ps + er * 32 + u;
            ull s0 = pp[0],       s1 = pp[512];
            ull s2 = pp[2 * 512], s3 = pp[3 * 512];
            ull s4 = pp[4 * 512], s5 = pp[5 * 512];
            ull s6 = pp[6 * 512], s7 = pp[7 * 512];
            ADD2(s0, s1); ADD2(s2, s3); ADD2(s4, s5); ADD2(s6, s7);
            ADD2(s0, s2); ADD2(s4, s6); ADD2(s0, s4);
            float sf = __uint_as_float((unsigned)(s0 & 0xffffffffu));
            float si = __uint_as_float((unsigned)(s0 >> 32));
            float gf   = q ? gfB : gfA;
            float gi   = q ? giB : giA;
            float ct   = q ? ctB : ctA;
            float Cold = q ? ColdB : ColdA;
            float f  = sigf(gf + sf);
            float ig = sigf(gi + si);
            float Cn = (tok > 0) ? fmaf(Cold, f, ct * ig) : 0.0f;
            __stcg(&CTdst[(u0 + u) * Bn + eb], Cn);
        }

        // ---- row-group barrier (16 blocks share this counter) ----
        __syncthreads();
        if (tid == 0) {
            __threadfence();                       // release C writes
            atomicAdd(barp, 1u);
            unsigned target = (unsigned)(t + 1) * 16u;
            while (*((volatile unsigned int*)barp) < target) { __nanosleep(20); }
            __threadfence();                       // acquire
        }
        __syncthreads();
    }
}

// ---------------- final: o gate + h = tanh(C_T)*o ----------------
__global__ void k_final_h(const int* __restrict__ xIdx, const float* __restrict__ Woc) {
    __shared__ float cps[Hn];
    int b = blockIdx.x;
    int tid = threadIdx.x;                         // 128
    const float* CTprev = d_CT[(Tn - 1) & 1];      // C_{T-1}, [h][b]
    const float* CTlast = d_CT[Tn & 1];            // C_T,     [h][b]
    for (int k = tid; k < Hn; k += 128) cps[k] = CTprev[k * Bn + b];
    __syncthreads();
    int tok = xIdx[b * Tn + (Tn - 1)];
    float acc[4] = {0.f, 0.f, 0.f, 0.f};
    #pragma unroll 4
    for (int k = 0; k < Hn; k++) {
        float c = cps[k];
        const float* wr = Woc + k * Hn + tid;
        acc[0] = fmaf(c, wr[0],   acc[0]);
        acc[1] = fmaf(c, wr[128], acc[1]);
        acc[2] = fmaf(c, wr[256], acc[2]);
        acc[3] = fmaf(c, wr[384], acc[3]);
    }
    #pragma unroll
    for (int m = 0; m < 4; m++) {
        int h = tid + m * 128;
        float o = sigf(d_gtab[tok * 2048 + 1024 + h] + acc[m]);
        d_Hf[b * Hn + h] = tanhf(CTlast[h * Bn + b]) * o;
    }
}

// ---------------- final: logits + log_softmax ----------------
__global__ void k_final_p(const float* __restrict__ Wph, const float* __restrict__ bp,
                          float* __restrict__ out) {
    __shared__ float hs[Hn];
    __shared__ float red[128];
    int b = blockIdx.x;
    int tid = threadIdx.x;                         // 128
    for (int k = tid; k < Hn; k += 128) hs[k] = d_Hf[b * Hn + k];
    __syncthreads();
    float p = -INFINITY;
    if (tid < NCn) {
        p = bp[tid];
        #pragma unroll 4
        for (int k = 0; k < Hn; k++) p = fmaf(hs[k], Wph[k * NCn + tid], p);
    }
    red[tid] = p;
    __syncthreads();
    for (int s = 64; s > 0; s >>= 1) {
        if (tid < s) red[tid] = fmaxf(red[tid], red[tid + s]);
        __syncthreads();
    }
    float mx = red[0];
    __syncthreads();
    red[tid] = (tid < NCn) ? expf(p - mx) : 0.0f;
    __syncthreads();
    for (int s = 64; s > 0; s >>= 1) {
        if (tid < s) red[tid] += red[tid + s];
        __syncthreads();
    }
    float lse = mx + logf(red[0]);
    if (tid < NCn) out[b * NCn + tid] = p - lse;
}

// ---------------- launch ----------------
extern "C" void kernel_launch(void* const* d_in, const int* in_sizes, int n_in,
                              void* d_out, int out_size) {
    (void)in_sizes; (void)n_in; (void)out_size;
    const int*   x   = (const int*)  d_in[0];
    const float* emb = (const float*)d_in[1];
    const float* Wfx = (const float*)d_in[2];
    const float* Wfc = (const float*)d_in[3];
    const float* bf  = (const float*)d_in[4];
    const float* Wix = (const float*)d_in[5];
    const float* Wic = (const float*)d_in[6];
    const float* bi  = (const float*)d_in[7];
    const float* Wox = (const float*)d_in[8];
    const float* Woc = (const float*)d_in[9];
    const float* bo  = (const float*)d_in[10];
    const float* Wcx = (const float*)d_in[11];
    const float* bc  = (const float*)d_in[12];
    const float* Wph = (const float*)d_in[13];
    const float* bp  = (const float*)d_in[14];
    float* out = (float*)d_out;

    cudaFuncSetAttribute(k_recur, cudaFuncAttributeMaxDynamicSharedMemorySize, SMEM_R_BYTES);

    k_init<<<(Bn * Hn + 255) / 256, 256>>>();
    k_gtab<<<Vn, 256>>>(emb, Wfx, bf, Wix, bi, Wox, bo, Wcx, bc);
    k_wpack<<<(Hn * Hn + 255) / 256, 256>>>(Wfc, Wic);
    k_recur<<<GRID_R, THR_R, SMEM_R_BYTES>>>(x);
    k_final_h<<<Bn, 128>>>(x, Woc);
    k_final_p<<<Bn, 128>>>(Wph, bp, out);
}